// round 6
// baseline (speedup 1.0000x reference)
#include <cuda_runtime.h>
#include <cstdint>
#include <cstddef>

// Problem dims
#define BB 16
#define TT 4096
#define DD 512
#define HH 512
#define NC 1536   // 3*H

typedef unsigned long long ull;

// ---------------- scratch (device globals: no runtime allocation allowed) ---
__device__ float g_xk[(size_t)BB * TT * NC];   // 402 MB: x @ kernel + bias0

// ---------------- f32x2 packed-math helpers (sm_103a) -----------------------
__device__ __forceinline__ ull pk2(float lo, float hi) {
    ull r;
    asm("mov.b64 %0, {%1, %2};" : "=l"(r) : "f"(lo), "f"(hi));
    return r;
}
__device__ __forceinline__ void unpk2(float& lo, float& hi, ull v) {
    asm("mov.b64 {%0, %1}, %2;" : "=f"(lo), "=f"(hi) : "l"(v));
}
__device__ __forceinline__ ull fma2(ull a, ull b, ull c) {
    ull d;
    asm("fma.rn.f32x2 %0, %1, %2, %3;" : "=l"(d) : "l"(a), "l"(b), "l"(c));
    return d;
}
__device__ __forceinline__ float sigmoid_f(float x) {
    return 1.f / (1.f + __expf(-x));
}
__device__ __forceinline__ float tanh_f(float x) {
    float e = __expf(2.f * x);
    return (e - 1.f) / (e + 1.f);
}
__device__ __forceinline__ uint32_t smem_u32(const void* p) {
    uint32_t a;
    asm("{ .reg .u64 t; cvta.to.shared.u64 t, %1; cvt.u32.u64 %0, t; }"
        : "=r"(a) : "l"(p));
    return a;
}
__device__ __forceinline__ uint32_t mapa_u32(uint32_t addr, uint32_t rank) {
    uint32_t r;
    asm("mapa.shared::cluster.u32 %0, %1, %2;" : "=r"(r) : "r"(addr), "r"(rank));
    return r;
}

// ============================================================================
// Phase 1: xk[m][n] = sum_k x[m][k] * W[k][n] + bias0[n]
// Tile 128x128x16, 256 thr, 8x8 micro, packed fma.rn.f32x2.
// ============================================================================
#define BM 128
#define BN 128
#define BK 16

__global__ void __launch_bounds__(256, 2)
gemm_xk_kernel(const float* __restrict__ A,
               const float* __restrict__ W,
               const float* __restrict__ bias)
{
    __shared__ float As[BK][BM];
    __shared__ float Bs[BK][BN];

    const int bm  = blockIdx.y * BM;
    const int bn  = blockIdx.x * BN;
    const int tid = threadIdx.x;
    const int tx  = tid & 15;
    const int ty  = tid >> 4;

    ull accp[8][4];
#pragma unroll
    for (int i = 0; i < 8; i++)
#pragma unroll
        for (int j = 0; j < 4; j++) accp[i][j] = 0ull;

    for (int kt = 0; kt < DD; kt += BK) {
#pragma unroll
        for (int i = 0; i < 2; i++) {
            int idx = tid * 2 + i;
            int m   = idx >> 2;
            int k4  = (idx & 3) << 2;
            float4 v = *(const float4*)&A[(size_t)(bm + m) * DD + kt + k4];
            As[k4 + 0][m] = v.x;
            As[k4 + 1][m] = v.y;
            As[k4 + 2][m] = v.z;
            As[k4 + 3][m] = v.w;
        }
#pragma unroll
        for (int i = 0; i < 2; i++) {
            int idx = tid * 2 + i;
            int k   = idx >> 5;
            int n4  = (idx & 31) << 2;
            *(float4*)&Bs[k][n4] =
                *(const float4*)&W[(size_t)(kt + k) * NC + bn + n4];
        }
        __syncthreads();

#pragma unroll
        for (int k = 0; k < BK; k++) {
            float4 av0 = *(const float4*)&As[k][ty * 8];
            float4 av1 = *(const float4*)&As[k][ty * 8 + 4];
            ulonglong2 bv0 = *(const ulonglong2*)&Bs[k][tx * 8];
            ulonglong2 bv1 = *(const ulonglong2*)&Bs[k][tx * 8 + 4];
            ull bp0 = bv0.x, bp1 = bv0.y, bp2 = bv1.x, bp3 = bv1.y;
            float a[8] = {av0.x, av0.y, av0.z, av0.w,
                          av1.x, av1.y, av1.z, av1.w};
#pragma unroll
            for (int i = 0; i < 8; i++) {
                ull ap = pk2(a[i], a[i]);
                accp[i][0] = fma2(ap, bp0, accp[i][0]);
                accp[i][1] = fma2(ap, bp1, accp[i][1]);
                accp[i][2] = fma2(ap, bp2, accp[i][2]);
                accp[i][3] = fma2(ap, bp3, accp[i][3]);
            }
        }
        __syncthreads();
    }

#pragma unroll
    for (int i = 0; i < 8; i++) {
        int m = bm + ty * 8 + i;
#pragma unroll
        for (int jp = 0; jp < 2; jp++) {
            int n = bn + tx * 8 + jp * 4;
            float l0, h0, l1, h1;
            unpk2(l0, h0, accp[i][jp * 2 + 0]);
            unpk2(l1, h1, accp[i][jp * 2 + 1]);
            float4 v;
            v.x = l0 + bias[n + 0];
            v.y = h0 + bias[n + 1];
            v.z = l1 + bias[n + 2];
            v.w = h1 + bias[n + 3];
            *(float4*)&g_xk[(size_t)m * NC + n] = v;
        }
    }
}

// ============================================================================
// Phase 2: persistent GRU recurrence — U in registers, DSMEM st.async handoff.
//   8 clusters x 16 CTAs. Cluster g owns batches {2g,2g+1}; rank c owns units
//   [32c,32c+32). 512 threads: thread (u=lane, ks=warp) holds U[k0..k0+32)
//   for unit u's 3 gate columns as 48 f32x2 registers.
//   Sync: 16 per-source mbarriers per CTA. Warp ks consumes only rank ks's
//   64 h-values; its lane0 sets arrive.expect_tx(256B) each phase. Producers
//   (gate warps, 64 threads) push h' to every rank's h_s[par^1] slot via
//   st.async.shared::cluster.mbarrier::complete_tx::bytes — data + completion
//   in one op, no fences, no atomics, no global memory.
//   Double-buffer anti-hazard is enforced transitively by the data deps
//   (skew bounded to 1 step); producers at most 1 phase ahead (negative
//   pending tx on the mbarrier absorbs it).
// ============================================================================
__global__ void __launch_bounds__(512, 1)
gru_rec_kernel(const float* __restrict__ RK,
               const float* __restrict__ bias,
               float* __restrict__ out)
{
    __shared__ float h_s[2][2][HH];        // [parity][batch][k]   (8 KB)
    __shared__ float red[16][32][7];       // [ks][u][gate*2+b]
    __shared__ float rb_s[96];             // recurrent bias slice
    __shared__ __align__(8) ull mbar[16];  // per-source-rank barriers

    const int bx  = blockIdx.x;
    const int g   = bx >> 4;               // cluster 0..7
    const int c   = bx & 15;               // rank in cluster 0..15
    const int tid = threadIdx.x;
    const int u   = tid & 31;              // lane
    const int ks  = tid >> 5;              // warp / K-split 0..15
    const int jb  = c * 32;                // first unit owned
    const int b0  = g * 2;                 // first global batch
    const int k0  = ks * 32;               // this warp's K chunk

    // ---- Load U slice into registers ---------------------------------------
    ull ureg[3][16];
#pragma unroll
    for (int gi = 0; gi < 3; gi++)
#pragma unroll
        for (int i = 0; i < 16; i++) {
            int k = k0 + 2 * i;
            float lo = RK[(size_t)k       * NC + gi * HH + jb + u];
            float hi = RK[(size_t)(k + 1) * NC + gi * HH + jb + u];
            ureg[gi][i] = pk2(lo, hi);
        }
    if (tid < 96)
        rb_s[tid] = bias[NC + (tid >> 5) * HH + jb + (tid & 31)];
    for (int i = tid; i < 2 * 2 * HH; i += 512)
        ((float*)h_s)[i] = 0.f;            // h0 = zeros (both parities)
    if (tid < 16) {                        // init per-source barriers, count=1
        uint32_t a = smem_u32(&mbar[tid]);
        asm volatile("mbarrier.init.shared.b64 [%0], 1;" :: "r"(a) : "memory");
    }
    __syncthreads();
    // All CTAs' smem + barriers ready before any remote push.
    asm volatile("barrier.cluster.arrive.aligned;" ::: "memory");
    asm volatile("barrier.cluster.wait.aligned;"  ::: "memory");

    const uint32_t my_mbar = smem_u32(&mbar[ks]);   // the barrier I wait on
    const uint32_t PAR_OFF = 2 * HH * 4;            // bytes between parities

    // Producer-side precomputed local addresses (gate warps only).
    uint32_t slot_l0 = 0, mbar_src_l = 0;
    if (ks < 2) {
        slot_l0    = smem_u32(&h_s[0][ks][jb + u]); // my value's slot, par 0
        mbar_src_l = smem_u32(&mbar[c]);            // barrier indexed by MY rank
    }

    float h_old = 0.f;

    // xk prefetch for t = 0 (gate warps only)
    float xz = 0.f, xr = 0.f, xh = 0.f;
    size_t xbase0 = 0;
    if (ks < 2) {
        xbase0 = ((size_t)(b0 + ks) * TT) * NC + jb + u;
        xz = g_xk[xbase0];
        xr = g_xk[xbase0 + HH];
        xh = g_xk[xbase0 + 2 * HH];
    }

    for (int t = 0; t < TT; t++) {
        const int par = t & 1;

        // Set this phase's expected bytes on my source barrier (64 x 4B).
        if (u == 0)
            asm volatile("mbarrier.arrive.expect_tx.shared.b64 _, [%0], 256;"
                         :: "r"(my_mbar) : "memory");

        // ---- packed dot over own 32-wide K chunk ---------------------------
        const ull* hp0 = (const ull*)&h_s[par][0][k0];
        const ull* hp1 = (const ull*)&h_s[par][1][k0];
        ull a0 = 0, a1 = 0, a2 = 0, a3 = 0, a4 = 0, a5 = 0;
#pragma unroll
        for (int i = 0; i < 16; i++) {
            ull h0 = hp0[i];               // broadcast LDS.64
            ull h1 = hp1[i];
            a0 = fma2(ureg[0][i], h0, a0);
            a1 = fma2(ureg[1][i], h0, a1);
            a2 = fma2(ureg[2][i], h0, a2);
            a3 = fma2(ureg[0][i], h1, a3);
            a4 = fma2(ureg[1][i], h1, a4);
            a5 = fma2(ureg[2][i], h1, a5);
        }
        {
            float lo, hi;
            unpk2(lo, hi, a0); red[ks][u][0] = lo + hi;   // z, b0
            unpk2(lo, hi, a1); red[ks][u][2] = lo + hi;   // r, b0
            unpk2(lo, hi, a2); red[ks][u][4] = lo + hi;   // h, b0
            unpk2(lo, hi, a3); red[ks][u][1] = lo + hi;   // z, b1
            unpk2(lo, hi, a4); red[ks][u][3] = lo + hi;   // r, b1
            unpk2(lo, hi, a5); red[ks][u][5] = lo + hi;   // h, b1
        }
        __syncthreads();

        // ---- gate warps: reduce + gates + st.async push --------------------
        if (ks < 2) {
            float s0 = 0.f, s1 = 0.f, s2 = 0.f;
#pragma unroll
            for (int q = 0; q < 16; q++) {
                s0 += red[q][u][0 + ks];
                s1 += red[q][u][2 + ks];
                s2 += red[q][u][4 + ks];
            }
            s0 += rb_s[u];
            s1 += rb_s[32 + u];
            s2 += rb_s[64 + u];

            float z    = sigmoid_f(xz + s0);
            float r    = sigmoid_f(xr + s1);
            float cand = tanh_f(xh + r * s2);
            float hn   = z * h_old + (1.f - z) * cand;
            h_old = hn;

            int gb = b0 + ks;
            out[((size_t)gb * TT + t) * HH + jb + u] = hn;
            if (t == TT - 1)
                out[(size_t)BB * TT * HH + (size_t)gb * HH + jb + u] = hn;

            // prefetch next step's xk
            {
                size_t nb = xbase0 + (size_t)((t + 1 < TT) ? t + 1 : t) * NC;
                xz = g_xk[nb];
                xr = g_xk[nb + HH];
                xh = g_xk[nb + 2 * HH];
            }

            // Push h' to every rank's h_s[par^1] slot; completion lands on
            // the destination's mbar[c] (my rank's barrier over there).
            uint32_t laddr = slot_l0 + (par ^ 1) * PAR_OFF;
            uint32_t vbits = __float_as_uint(hn);
#pragma unroll
            for (int rk = 0; rk < 16; rk++) {
                uint32_t ra = mapa_u32(laddr, rk);
                uint32_t rm = mapa_u32(mbar_src_l, rk);
                asm volatile(
                    "st.async.weak.shared::cluster.mbarrier::complete_tx::bytes.b32 "
                    "[%0], %1, [%2];"
                    :: "r"(ra), "r"(vbits), "r"(rm) : "memory");
            }
        }

        // ---- wait for my source rank's 64 values (parity = t&1) ------------
        {
            uint32_t done;
            asm volatile(
                "{\n\t"
                ".reg .pred p;\n\t"
                "mbarrier.try_wait.parity.acquire.cluster.shared::cta.b64 p, [%1], %2;\n\t"
                "selp.b32 %0, 1, 0, p;\n\t"
                "}"
                : "=r"(done) : "r"(my_mbar), "r"((uint32_t)par) : "memory");
            if (!done) {
                asm volatile(
                    "{\n\t"
                    ".reg .pred P1;\n\t"
                    "WL_%=:\n\t"
                    "mbarrier.try_wait.parity.acquire.cluster.shared::cta.b64 P1, [%0], %1, 0x989680;\n\t"
                    "@P1 bra.uni WD_%=;\n\t"
                    "bra.uni WL_%=;\n\t"
                    "WD_%=:\n\t"
                    "}"
                    :: "r"(my_mbar), "r"((uint32_t)par) : "memory");
            }
        }
    }

    // No CTA may exit while peers' st.async into its smem could be in flight.
    asm volatile("barrier.cluster.arrive.aligned;" ::: "memory");
    asm volatile("barrier.cluster.wait.aligned;"  ::: "memory");
}

// ============================================================================
extern "C" void kernel_launch(void* const* d_in, const int* in_sizes, int n_in,
                              void* d_out, int out_size)
{
    const float* x    = (const float*)d_in[0];   // [16,4096,512]
    const float* Wk   = (const float*)d_in[1];   // [512,1536]
    const float* RK   = (const float*)d_in[2];   // [512,1536]
    const float* bias = (const float*)d_in[3];   // [2,1536]
    float* out = (float*)d_out;                  // outputs ++ state

    // Phase 1: input projection GEMM.
    dim3 grid1(NC / BN, (BB * TT) / BM);
    gemm_xk_kernel<<<grid1, 256>>>(x, Wk, bias);

    // Phase 2: persistent recurrence, 8 clusters x 16 CTAs (nonportable).
    static int attr_done = 0;
    if (!attr_done) {
        cudaFuncSetAttribute(gru_rec_kernel,
                             cudaFuncAttributeNonPortableClusterSizeAllowed, 1);
        attr_done = 1;
    }

    cudaLaunchConfig_t cfg = {};
    cfg.gridDim  = dim3(128, 1, 1);
    cfg.blockDim = dim3(512, 1, 1);
    cfg.dynamicSmemBytes = 0;
    cfg.stream = 0;
    cudaLaunchAttribute attrs[1];
    attrs[0].id = cudaLaunchAttributeClusterDimension;
    attrs[0].val.clusterDim.x = 16;
    attrs[0].val.clusterDim.y = 1;
    attrs[0].val.clusterDim.z = 1;
    cfg.attrs = attrs;
    cfg.numAttrs = 1;
    cudaLaunchKernelEx(&cfg, gru_rec_kernel, RK, bias, out);
}

// round 10
// speedup vs baseline: 1.6801x; 1.6801x over previous
#include <cuda_runtime.h>
#include <cstdint>
#include <cstddef>

// Problem dims
#define BB 16
#define TT 4096
#define DD 512
#define HH 512
#define NC 1536   // 3*H

typedef unsigned long long ull;

// ---------------- scratch (device globals: no runtime allocation allowed) ---
__device__ float g_xk[(size_t)BB * TT * NC];   // 402 MB: x @ kernel + bias0
__device__ float g_hbuf[2][BB][HH];            // double-buffered hidden state
__device__ int   g_ctr[8 * TT];                // per-group per-step arrivals

// ---------------- f32x2 packed-math helpers (sm_103a) -----------------------
__device__ __forceinline__ ull pk2(float lo, float hi) {
    ull r;
    asm("mov.b64 %0, {%1, %2};" : "=l"(r) : "f"(lo), "f"(hi));
    return r;
}
__device__ __forceinline__ void unpk2(float& lo, float& hi, ull v) {
    asm("mov.b64 {%0, %1}, %2;" : "=f"(lo), "=f"(hi) : "l"(v));
}
__device__ __forceinline__ ull fma2(ull a, ull b, ull c) {
    ull d;
    asm("fma.rn.f32x2 %0, %1, %2, %3;" : "=l"(d) : "l"(a), "l"(b), "l"(c));
    return d;
}
__device__ __forceinline__ float sigmoid_f(float x) {
    return 1.f / (1.f + __expf(-x));
}
__device__ __forceinline__ float tanh_f(float x) {
    float e = __expf(2.f * x);
    return (e - 1.f) / (e + 1.f);
}

// ============================================================================
// Phase 1: xk[m][n] = sum_k x[m][k] * W[k][n] + bias0[n]
// M = B*T = 65536, K = 512, N = 1536.  Tile 128x128x16, 256 thr, 8x8 micro,
// packed fma.rn.f32x2 inner product.
// ============================================================================
#define BM 128
#define BN 128
#define BK 16

__global__ void __launch_bounds__(256, 2)
gemm_xk_kernel(const float* __restrict__ A,
               const float* __restrict__ W,
               const float* __restrict__ bias)
{
    __shared__ float As[BK][BM];   // A tile transposed: As[k][m]
    __shared__ float Bs[BK][BN];   // Bs[k][n]

    const int bm  = blockIdx.y * BM;
    const int bn  = blockIdx.x * BN;
    const int tid = threadIdx.x;
    const int tx  = tid & 15;
    const int ty  = tid >> 4;

    ull accp[8][4];
#pragma unroll
    for (int i = 0; i < 8; i++)
#pragma unroll
        for (int j = 0; j < 4; j++) accp[i][j] = 0ull;

    for (int kt = 0; kt < DD; kt += BK) {
#pragma unroll
        for (int i = 0; i < 2; i++) {
            int idx = tid * 2 + i;
            int m   = idx >> 2;
            int k4  = (idx & 3) << 2;
            float4 v = *(const float4*)&A[(size_t)(bm + m) * DD + kt + k4];
            As[k4 + 0][m] = v.x;
            As[k4 + 1][m] = v.y;
            As[k4 + 2][m] = v.z;
            As[k4 + 3][m] = v.w;
        }
#pragma unroll
        for (int i = 0; i < 2; i++) {
            int idx = tid * 2 + i;
            int k   = idx >> 5;
            int n4  = (idx & 31) << 2;
            *(float4*)&Bs[k][n4] =
                *(const float4*)&W[(size_t)(kt + k) * NC + bn + n4];
        }
        __syncthreads();

#pragma unroll
        for (int k = 0; k < BK; k++) {
            float4 av0 = *(const float4*)&As[k][ty * 8];
            float4 av1 = *(const float4*)&As[k][ty * 8 + 4];
            ulonglong2 bv0 = *(const ulonglong2*)&Bs[k][tx * 8];
            ulonglong2 bv1 = *(const ulonglong2*)&Bs[k][tx * 8 + 4];
            ull bp0 = bv0.x, bp1 = bv0.y, bp2 = bv1.x, bp3 = bv1.y;
            float a[8] = {av0.x, av0.y, av0.z, av0.w,
                          av1.x, av1.y, av1.z, av1.w};
#pragma unroll
            for (int i = 0; i < 8; i++) {
                ull ap = pk2(a[i], a[i]);
                accp[i][0] = fma2(ap, bp0, accp[i][0]);
                accp[i][1] = fma2(ap, bp1, accp[i][1]);
                accp[i][2] = fma2(ap, bp2, accp[i][2]);
                accp[i][3] = fma2(ap, bp3, accp[i][3]);
            }
        }
        __syncthreads();
    }

#pragma unroll
    for (int i = 0; i < 8; i++) {
        int m = bm + ty * 8 + i;
#pragma unroll
        for (int jp = 0; jp < 2; jp++) {
            int n = bn + tx * 8 + jp * 4;
            float l0, h0, l1, h1;
            unpk2(l0, h0, accp[i][jp * 2 + 0]);
            unpk2(l1, h1, accp[i][jp * 2 + 1]);
            float4 v;
            v.x = l0 + bias[n + 0];
            v.y = h0 + bias[n + 1];
            v.z = l1 + bias[n + 2];
            v.w = h1 + bias[n + 3];
            *(float4*)&g_xk[(size_t)m * NC + n] = v;
        }
    }
}

// ============================================================================
// Phase 2: persistent GRU recurrence — U in registers, release/acquire sync.
//   8 groups x 16 CTAs; group g owns batches {2g,2g+1}; CTA c owns units
//   [32c,32c+32). 512 threads: thread (u = lane, ks = warp) holds the
//   U[k0..k0+32) slice for unit u's 3 gate columns as 48 f32x2 registers.
//   Per step (identical structure to the proven R5 kernel):
//     dot (LDS.64 broadcast of own h chunk, 96 FFMA2) -> red[] -> barrier
//     gate warps (ks<2): 16-way reduce, gates, STG h' to g_hbuf[par^1],
//       __syncwarp, lane0 red.release.gpu (release replaces the MEMBAR)
//     every warp: FUSED poll — each iteration acquire-loads ctr then ld.cg
//       loads its OWN 64-float h chunk; when ctr reads 32 the chunk load in
//       that iteration was issued after the acquire -> already valid. No
//       MEMBARs anywhere; the dependent second L2 round trip is gone.
//   red[] single-buffered is safe exactly as in R5: a consumer cannot pass
//   the poll (ctr==32) until every gate warp in the group has RED'd, which
//   happens only after those warps finished reading red[].
// ============================================================================
__global__ void __launch_bounds__(512, 1)
gru_rec_kernel(const float* __restrict__ RK,
               const float* __restrict__ bias,
               float* __restrict__ out)
{
    __shared__ float red[16][32][7];       // [ks][u][gate*2+b]
    __shared__ float h_chunk[16][2][32];   // per-warp private h slice
    __shared__ float rb_s[96];             // recurrent bias slice

    const int bx  = blockIdx.x;
    const int g   = bx >> 4;               // group 0..7
    const int c   = bx & 15;               // cta-in-group 0..15
    const int tid = threadIdx.x;
    const int u   = tid & 31;              // lane
    const int ks  = tid >> 5;              // warp / K-split 0..15
    const int jb  = c * 32;                // first unit owned
    const int b0  = g * 2;                 // first global batch
    const int k0  = ks * 32;               // this warp's K chunk

    // ---- Load U slice into registers ---------------------------------------
    ull ureg[3][16];
#pragma unroll
    for (int gi = 0; gi < 3; gi++)
#pragma unroll
        for (int i = 0; i < 16; i++) {
            int k = k0 + 2 * i;
            float lo = RK[(size_t)k       * NC + gi * HH + jb + u];
            float hi = RK[(size_t)(k + 1) * NC + gi * HH + jb + u];
            ureg[gi][i] = pk2(lo, hi);
        }
    if (tid < 96)
        rb_s[tid] = bias[NC + (tid >> 5) * HH + jb + (tid & 31)];
    // zero own h chunk (h0 = 0)
    for (int i = u; i < 64; i += 32) ((float*)h_chunk[ks])[i] = 0.f;
    __syncthreads();

    int* ctr = &g_ctr[g * TT];

    // reload-phase lane mapping: lane -> (batch, pair-index)
    const int rl_b = u >> 4;               // 0..1
    const int rl_l = u & 15;               // 0..15

    float h_old = 0.f;                     // gate threads: own h from last step

    // xk prefetch for t = 0 (gate warps only)
    float xz = 0.f, xr = 0.f, xh = 0.f;
    size_t xbase0 = 0;
    if (ks < 2) {
        xbase0 = ((size_t)(b0 + ks) * TT) * NC + jb + u;
        xz = g_xk[xbase0];
        xr = g_xk[xbase0 + HH];
        xh = g_xk[xbase0 + 2 * HH];
    }

    for (int t = 0; t < TT; t++) {
        // ---- packed dot over own 32-wide K chunk ---------------------------
        const ull* hp0 = (const ull*)h_chunk[ks][0];
        const ull* hp1 = (const ull*)h_chunk[ks][1];
        ull a0 = 0, a1 = 0, a2 = 0, a3 = 0, a4 = 0, a5 = 0;
#pragma unroll
        for (int i = 0; i < 16; i++) {
            ull h0 = hp0[i];               // broadcast LDS.64
            ull h1 = hp1[i];
            a0 = fma2(ureg[0][i], h0, a0);
            a1 = fma2(ureg[1][i], h0, a1);
            a2 = fma2(ureg[2][i], h0, a2);
            a3 = fma2(ureg[0][i], h1, a3);
            a4 = fma2(ureg[1][i], h1, a4);
            a5 = fma2(ureg[2][i], h1, a5);
        }
        {
            float lo, hi;
            unpk2(lo, hi, a0); red[ks][u][0] = lo + hi;   // z, b0
            unpk2(lo, hi, a1); red[ks][u][2] = lo + hi;   // r, b0
            unpk2(lo, hi, a2); red[ks][u][4] = lo + hi;   // h, b0
            unpk2(lo, hi, a3); red[ks][u][1] = lo + hi;   // z, b1
            unpk2(lo, hi, a4); red[ks][u][3] = lo + hi;   // r, b1
            unpk2(lo, hi, a5); red[ks][u][5] = lo + hi;   // h, b1
        }
        __syncthreads();

        // ---- gate warps: reduce + gates + publish + release-signal ---------
        if (ks < 2) {
            float s0 = 0.f, s1 = 0.f, s2 = 0.f;
#pragma unroll
            for (int q = 0; q < 16; q++) {
                s0 += red[q][u][0 + ks];
                s1 += red[q][u][2 + ks];
                s2 += red[q][u][4 + ks];
            }
            s0 += rb_s[u];
            s1 += rb_s[32 + u];
            s2 += rb_s[64 + u];

            float z    = sigmoid_f(xz + s0);
            float r    = sigmoid_f(xr + s1);
            float cand = tanh_f(xh + r * s2);
            float hn   = z * h_old + (1.f - z) * cand;
            h_old = hn;

            int gb = b0 + ks;
            out[((size_t)gb * TT + t) * HH + jb + u] = hn;
            if (t == TT - 1)
                out[(size_t)BB * TT * HH + (size_t)gb * HH + jb + u] = hn;
            asm volatile("st.global.cg.f32 [%0], %1;"
                         :: "l"(&g_hbuf[(t + 1) & 1][gb][jb + u]), "f"(hn)
                         : "memory");

            // prefetch next step's xk (consumed next iteration)
            {
                size_t nb = xbase0 + (size_t)((t + 1 < TT) ? t + 1 : t) * NC;
                xz = g_xk[nb];
                xr = g_xk[nb + HH];
                xh = g_xk[nb + 2 * HH];
            }

            __syncwarp();                  // warp stores HB-before lane0's RED
            if (u == 0)
                asm volatile("red.release.gpu.global.add.s32 [%0], %1;"
                             :: "l"(&ctr[t]), "r"(1) : "memory");
        }

        // ---- fused acquire-poll + own-chunk reload -------------------------
        {
            const float* src = &g_hbuf[(t + 1) & 1][b0 + rl_b][k0 + 2 * rl_l];
            int cv;
            ull v;
            do {
                asm volatile("ld.acquire.gpu.global.b32 %0, [%1];"
                             : "=r"(cv) : "l"(&ctr[t]) : "memory");
                asm volatile("ld.global.cg.b64 %0, [%1];"
                             : "=l"(v) : "l"(src) : "memory");
            } while (cv != 32);
            // loop exits => the b64 load above was issued after a successful
            // acquire of ctr==32, so v is the committed h' value.
            *(ull*)&h_chunk[ks][rl_b][2 * rl_l] = v;
        }
        __syncwarp();
    }
}

// ============================================================================
extern "C" void kernel_launch(void* const* d_in, const int* in_sizes, int n_in,
                              void* d_out, int out_size)
{
    const float* x    = (const float*)d_in[0];   // [16,4096,512]
    const float* Wk   = (const float*)d_in[1];   // [512,1536]
    const float* RK   = (const float*)d_in[2];   // [512,1536]
    const float* bias = (const float*)d_in[3];   // [2,1536]
    float* out = (float*)d_out;                  // outputs ++ state

    // Zero the barrier counters (memset node; re-zeroed per graph replay).
    void* ctr_ptr = nullptr;
    cudaGetSymbolAddress(&ctr_ptr, g_ctr);
    cudaMemsetAsync(ctr_ptr, 0, sizeof(int) * 8 * TT);

    // Phase 1: input projection GEMM.
    dim3 grid1(NC / BN, (BB * TT) / BM);
    gemm_xk_kernel<<<grid1, 256>>>(x, Wk, bias);

    // Phase 2: persistent recurrence.
    gru_rec_kernel<<<128, 512>>>(RK, bias, out);
}